// round 14
// baseline (speedup 1.0000x reference)
#include <cuda_runtime.h>

#define CUT2 25.0f
#define HCAP 128        // per-warp staged-hit capacity (max row degree ~60)
#define NROWS_CAP 65536
#define NGRP_CAP  (NROWS_CAP / 4)
#define MAXCH 32        // max 32-wide j-chunks per row (nat <= 1024)
#define NPK_CAP 131072
#define NSYS_CAP 2048
#define NSYS_SM 257

// Scratch (static __device__, allocation-free).
__device__ float4 g_pk[NPK_CAP];             // (2x,2y,2z,sq) per atom, padded
__device__ uint4  g_mask[(size_t)NGRP_CAP * MAXCH];      // R9 layout, 8 MB
__device__ unsigned char g_cntb[(size_t)MAXCH * NROWS_CAP]; // [chunk][row]
__device__ int    g_offsets[NROWS_CAP];      // within-system exclusive prefix
__device__ int    g_systot[NSYS_CAP];        // per-system totals

// ---- bit-exact reference arithmetic (DO NOT CHANGE) ----
__device__ __forceinline__ float sqnorm3(float x, float y, float z) {
    return __fadd_rn(__fadd_rn(__fmul_rn(x, x), __fmul_rn(y, y)), __fmul_rn(z, z));
}
// gram dot via GEMM-style FMA chain: c = rn(x*x'); c = fma(y,y',c); c = fma(z,z',c)
__device__ __forceinline__ float dot3(float4 a, float4 b) {
    return __fmaf_rn(a.z, b.z, __fmaf_rn(a.y, b.y, __fmul_rn(a.x, b.x)));
}
__device__ __forceinline__ float d12_of(float4 ai, float4 aj) {
    return __fsub_rn(__fadd_rn(ai.w, aj.w), __fmul_rn(2.0f, dot3(ai, aj)));
}
// --------------------------------------------------------

// K0: pack (2x, 2y, 2z, sq) per atom; sentinel (0,0,0,1e30) pads each system
// to a multiple of 32 so the sweep needs no bounds checks.
__global__ void prep_kernel(const float* __restrict__ coords, int nat,
                            int stride, int nsys) {
    int idx = blockIdx.x * blockDim.x + threadIdx.x;
    if (idx >= nsys * stride) return;
    int s = idx / stride, j = idx - s * stride;
    float4 r = make_float4(0.f, 0.f, 0.f, 1e30f);
    if (j < nat) {
        const float* p = coords + ((size_t)s * nat + j) * 3;
        float x = p[0], y = p[1], z = p[2];
        r = make_float4(2.0f * x, 2.0f * y, 2.0f * z, sqnorm3(x, y, z));
    }
    g_pk[idx] = r;
}

// K1: flat-balanced mask sweep. Work item = (64-row block b, chunk c), c in
// [2b, nch): uniform cost, enumerated flat -> perfect balance. Lane owns rows
// i0 = 64b+lane and i1 = i0+32; each broadcast __ldg of atom j serves both.
// Masks accumulate in registers (FSETP + predicated OR; no ballots). The
// negated/halved row regs make the FMA chain produce -2*dot exactly, so
// d = rn(rn(wi+wj) - 2*dot): bit-identical to the reference d12.
__global__ void __launch_bounds__(256, 4)
sweep_kernel(int nat, int nch, int ngroups, int NI, int nrowtot) {
    int lane = threadIdx.x & 31;
    int wj   = (threadIdx.x >> 5) + blockIdx.y * (blockDim.x >> 5);
    int W    = (blockDim.x >> 5) * gridDim.y;
    int s    = blockIdx.x;
    const float4* pk = g_pk + (size_t)s * (nch << 5);
    unsigned* mw = (unsigned*)g_mask;

    for (int it = wj; it < NI; it += W) {
        // decode flat triangle index -> (b, c)
        int rem = it, b = 0;
        while (rem >= nch - 2 * b) { rem -= nch - 2 * b; b++; }
        int c = 2 * b + rem;

        int i0 = (b << 6) + lane, i1 = i0 + 32;
        float4 v0 = pk[i0], v1 = pk[i1];
        float nx0 = -0.5f * v0.x, ny0 = -0.5f * v0.y, nz0 = -0.5f * v0.z;
        float w0 = v0.w;
        float nx1 = -0.5f * v1.x, ny1 = -0.5f * v1.y, nz1 = -0.5f * v1.z;
        float w1 = v1.w;

        const float4* jp = pk + (c << 5);
        unsigned m0 = 0, m1 = 0;
#pragma unroll
        for (int k = 0; k < 32; k++) {
            float4 aj = __ldg(&jp[k]);          // warp-broadcast, L1-resident
            float t0 = __fmul_rn(nx0, aj.x);
            t0 = __fmaf_rn(ny0, aj.y, t0);
            t0 = __fmaf_rn(nz0, aj.z, t0);
            float d0 = __fadd_rn(__fadd_rn(w0, aj.w), t0);
            if (d0 < CUT2) m0 |= (1u << k);
            float t1 = __fmul_rn(nx1, aj.x);
            t1 = __fmaf_rn(ny1, aj.y, t1);
            t1 = __fmaf_rn(nz1, aj.z, t1);
            float d1 = __fadd_rn(__fadd_rn(w1, aj.w), t1);
            if (d1 < CUT2) m1 |= (1u << k);
        }
        // Diagonal corrections (j > i half-list).
        if (c == (b << 1))     m0 &= (0xFFFFFFFEu << lane);
        if (c == (b << 1) + 1) m1 &= (0xFFFFFFFEu << lane);

        int g40 = i0 >> 2, g41 = i1 >> 2;
        if (g40 < ngroups)
            mw[(((size_t)s * ngroups + g40) * nch + c) * 4 + (i0 & 3)] = m0;
        if (i0 < nat)
            g_cntb[(size_t)c * nrowtot + s * nat + i0] =
                (unsigned char)__popc(m0);
        if (c > (b << 1)) {   // row1's chunks start at 2b+1
            if (g41 < ngroups)
                mw[(((size_t)s * ngroups + g41) * nch + c) * 4 + (i1 & 3)] = m1;
            if (i1 < nat)
                g_cntb[(size_t)c * nrowtot + s * nat + i1] =
                    (unsigned char)__popc(m1);
        }
    }
}

// K2: per-system exclusive scan; row count = sum of its chunk count-bytes
// (coalesced: consecutive threads read consecutive bytes per chunk column).
__global__ void scan_sys_kernel(int nat, int nch, int nrowtot) {
    __shared__ int wsum[32];
    int s = blockIdx.x;
    int tid = threadIdx.x;
    int lane = tid & 31, w = tid >> 5;

    int v = 0;
    if (tid < nat) {
        size_t base = (size_t)s * nat + tid;
        for (int c = tid >> 5; c < nch; c++)
            v += g_cntb[(size_t)c * nrowtot + base];
    }

    int x = v;
#pragma unroll
    for (int o = 1; o < 32; o <<= 1) {
        int u = __shfl_up_sync(0xffffffffu, x, o);
        if (lane >= o) x += u;
    }
    if (lane == 31) wsum[w] = x;
    __syncthreads();
    if (w == 0) {
        int y = wsum[lane];
#pragma unroll
        for (int o = 1; o < 32; o <<= 1) {
            int u = __shfl_up_sync(0xffffffffu, y, o);
            if (lane >= o) y += u;
        }
        wsum[lane] = y;
    }
    __syncthreads();
    int incl = x + ((w > 0) ? wsum[w - 1] : 0);
    if (tid < nat) g_offsets[s * nat + tid] = incl - v;
    if (tid == nat - 1) g_systot[s] = incl;
}

// K3: fused output (R13-proven). One warp per row; per-warp smem staging of
// hit j-indices, then lane k handles the k-th hit, recomputing d12 bit-
// exactly from __ldg coords. Pad blocks run concurrently.
// Output float32 layout (maxp = MAX_PAIRS):
//   [0,M): src   [M,2M): dst    (edge_src = concat(src,dst))
//   [2M,3M): dst [3M,4M): src   (edge_dst = concat(dst,src))
//   [4M,5M): d12 [5M,6M): d12   [6M]: npairs
__global__ void output_kernel(const float* __restrict__ coords,
                              float* __restrict__ out, int maxp, int nrows,
                              int nat, int nsys, int nch, int ngroups,
                              int WB, float padval, int vec_ok) {
    __shared__ int s_sysoff[NSYS_SM];
    __shared__ int s_hits[8][HCAP];
    int tid = threadIdx.x;
    if (tid < 32) {
        int per = (nsys + 31) >> 5;
        int bbase = tid * per;
        int loc[8];
        int sum = 0;
        for (int u = 0; u < per && u < 8; u++) {
            int idx = bbase + u;
            int t = (idx < nsys) ? g_systot[idx] : 0;
            loc[u] = sum;
            sum += t;
        }
        int x = sum;
#pragma unroll
        for (int o = 1; o < 32; o <<= 1) {
            int uu = __shfl_up_sync(0xffffffffu, x, o);
            if (tid >= o) x += uu;
        }
        int excl = x - sum;
        for (int u = 0; u < per && u < 8; u++) {
            int idx = bbase + u;
            if (idx < nsys && idx < NSYS_SM) s_sysoff[idx] = excl + loc[u];
        }
        if (tid == 31 && nsys < NSYS_SM) s_sysoff[nsys] = x;  // npairs
    }
    __syncthreads();
    int np = s_sysoff[nsys];

    if (blockIdx.x < WB) {
        int row = blockIdx.x * (blockDim.x >> 5) + (tid >> 5);
        if (row >= nrows) return;              // warp-uniform
        int lane = tid & 31;
        int w = tid >> 5;
        int s = row / nat, i = row - s * nat;
        int g = i >> 2, t = i & 3;
        int c0 = i >> 5;

        unsigned m = 0;
        if (lane >= c0 && lane < nch)
            m = ((const unsigned*)&g_mask[((size_t)s * ngroups + g) * nch])
                 [(lane << 2) + t];
        int cnt = __popc(m);

        int x = cnt;  // inclusive scan across lanes (chunks)
#pragma unroll
        for (int o = 1; o < 32; o <<= 1) {
            int u = __shfl_up_sync(0xffffffffu, x, o);
            if (lane >= o) x += u;
        }
        int mybase = x - cnt;
        int total = __shfl_sync(0xffffffffu, x, 31);
        if (total == 0) return;                 // warp-uniform

        {   // stage hit j-indices at their final in-row positions
            unsigned mm = m;
            int r = mybase;
            int jb = lane << 5;
            while (mm) {
                int b = __ffs(mm) - 1;
                mm &= mm - 1;
                if (r < HCAP) s_hits[w][r] = jb + b;
                r++;
            }
        }
        __syncwarp();

        const float* ci = coords + (size_t)row * 3;
        float xi = __ldg(ci), yi = __ldg(ci + 1), zi = __ldg(ci + 2);
        float4 ai = make_float4(xi, yi, zi, sqnorm3(xi, yi, zi));
        float fsrc = (float)row;
        float fsysbase = (float)(s * nat);
        int off = s_sysoff[s] + g_offsets[row];
        int sysbase = s * nat;

        for (int kb = 0; kb < total; kb += 32) {
            int k = kb + lane;
            if (k < total && k < HCAP) {
                int j = s_hits[w][k];
                const float* cj = coords + (size_t)(sysbase + j) * 3;
                float xj = __ldg(cj), yj = __ldg(cj + 1), zj = __ldg(cj + 2);
                float4 aj = make_float4(xj, yj, zj, sqnorm3(xj, yj, zj));
                float d = d12_of(ai, aj);
                int pos = off + k;
                if (pos < maxp) {
                    float fdst = fsysbase + (float)j;
                    out[pos]            = fsrc;
                    out[maxp + pos]     = fdst;
                    out[2 * maxp + pos] = fdst;
                    out[3 * maxp + pos] = fsrc;
                    out[4 * maxp + pos] = d;
                    out[5 * maxp + pos] = d;
                }
            }
        }
    } else {
        int pb = blockIdx.x - WB;
        if (pb == 0 && tid == 0) out[6 * maxp] = (float)np;
        int k0 = (pb * blockDim.x + tid) * 4;
        if (k0 >= maxp) return;
        if (k0 >= np && k0 + 3 < maxp && vec_ok) {
            float4 pv = make_float4(padval, padval, padval, padval);
            float4 cv = make_float4(CUT2, CUT2, CUT2, CUT2);
            *(float4*)(out + k0)            = pv;
            *(float4*)(out + maxp + k0)     = pv;
            *(float4*)(out + 2 * maxp + k0) = pv;
            *(float4*)(out + 3 * maxp + k0) = pv;
            *(float4*)(out + 4 * maxp + k0) = cv;
            *(float4*)(out + 5 * maxp + k0) = cv;
        } else {
#pragma unroll
            for (int u = 0; u < 4; u++) {
                int k = k0 + u;
                if (k < maxp && k >= np) {
                    out[k]            = padval;
                    out[maxp + k]     = padval;
                    out[2 * maxp + k] = padval;
                    out[3 * maxp + k] = padval;
                    out[4 * maxp + k] = CUT2;
                    out[5 * maxp + k] = CUT2;
                }
            }
        }
    }
}

extern "C" void kernel_launch(void* const* d_in, const int* in_sizes, int n_in,
                              void* d_out, int out_size) {
    const float* coords = (const float*)d_in[0];
    int n    = in_sizes[1];          // total atoms
    int nsys = in_sizes[2];          // systems
    int nat  = n / nsys;
    int maxp = (out_size - 1) / 6;   // MAX_PAIRS
    float* out = (float*)d_out;

    int nch = (nat + 31) >> 5;            // 32-wide j-chunks per row (<= 32)
    int ngroups = (nat + 3) >> 2;         // 4-row mask groups per system
    int stride = nch << 5;                // padded atoms per system
    int vec_ok = ((maxp & 3) == 0) ? 1 : 0;

    // flat triangle item count: (64-row block b, chunk c >= 2b)
    int NI = 0;
    for (int b = 0; 64 * b < nat; b++) {
        int cb = nch - 2 * b;
        if (cb > 0) NI += cb;
    }
    int gy = (NI + 15) / 16;              // 8 warps/block, 2 items/warp
    if (gy < 1) gy = 1;

    int WB = (n + 7) / 8;                          // write blocks (8 warps ea)
    int PB = (maxp + 256 * 4 - 1) / (256 * 4);     // pad blocks

    prep_kernel<<<(nsys * stride + 255) / 256, 256>>>(coords, nat, stride,
                                                      nsys);
    sweep_kernel<<<dim3(nsys, gy), 256>>>(nat, nch, ngroups, NI, n);
    scan_sys_kernel<<<nsys, 1024>>>(nat, nch, n);
    output_kernel<<<WB + PB, 256>>>(coords, out, maxp, n, nat, nsys, nch,
                                    ngroups, WB, (float)n, vec_ok);
}